// round 13
// baseline (speedup 1.0000x reference)
#include <cuda_runtime.h>
#include <cuda_fp16.h>

#define R_TOT   16384      // H*W rays
#define KPRIM   32
#define NSTEPS  64
#define DTSTEP  (1.0f/64.0f)
#define FXSCALE 1048576.0f         // 2^20 fixed-point scale for alpha redux
#define FXINV   (1.0f/1048576.0f)

// Packed template: per (k,z,y,x): {h2(r,g)@x, h2(b,a)@x, h2(r,g)@x+1, h2(b,a)@x+1} = 16B
__device__ uint4 g_tpair[KPRIM * 4096];   // 2 MB, L2-resident

// --- Prologue: pack template [K,4,16,16,16] fp32 -> channel-pair half2s ---
__global__ void pack_tmpl_kernel(const float* __restrict__ tmpl) {
    int idx = blockIdx.x * blockDim.x + threadIdx.x;
    if (idx >= KPRIM * 4096) return;
    int k = idx >> 12;
    int v = idx & 4095;            // z*256 + y*16 + x
    int x = v & 15;
    int x1 = (x < 15) ? 1 : 0;     // clamp x+1 (offset)
    const float* b = tmpl + (size_t)k * 4 * 4096;
    int p0 = v, p1 = v + x1;
    __half2 rg0 = __floats2half2_rn(b[p0],          b[4096 + p0]);
    __half2 ba0 = __floats2half2_rn(b[8192 + p0],   b[12288 + p0]);
    __half2 rg1 = __floats2half2_rn(b[p1],          b[4096 + p1]);
    __half2 ba1 = __floats2half2_rn(b[8192 + p1],   b[12288 + p1]);
    uint4 q;
    q.x = *(unsigned int*)&rg0;
    q.y = *(unsigned int*)&ba0;
    q.z = *(unsigned int*)&rg1;
    q.w = *(unsigned int*)&ba1;
    g_tpair[idx] = q;
}

__device__ __forceinline__ void xlerp_h2(uint4 q, __half2 fx2, __half2& rg, __half2& ba) {
    __half2 rg0 = *(__half2*)&q.x;
    __half2 ba0 = *(__half2*)&q.y;
    __half2 rg1 = *(__half2*)&q.z;
    __half2 ba1 = *(__half2*)&q.w;
    rg = __hfma2(fx2, __hsub2(rg1, rg0), rg0);
    ba = __hfma2(fx2, __hsub2(ba1, ba0), ba0);
}

// --- Main march: warp per ray, lane per prim, half2 tree, L1-prefetch distance 2 ---
__global__ void __launch_bounds__(64) march_kernel(
    const float* __restrict__ raypos,
    const float* __restrict__ raydir,
    const float* __restrict__ tminmax,
    const float* __restrict__ primpos,
    const float* __restrict__ primrot,
    const float* __restrict__ primscale,
    float* __restrict__ out)
{
    int gtid = blockIdx.x * blockDim.x + threadIdx.x;
    int ray  = gtid >> 5;
    int lane = threadIdx.x & 31;
    if (ray >= R_TOT) return;

    float rpx = raypos[ray * 3 + 0];
    float rpy = raypos[ray * 3 + 1];
    float rpz = raypos[ray * 3 + 2];
    float rdx = raydir[ray * 3 + 0];
    float rdy = raydir[ray * 3 + 1];
    float rdz = raydir[ray * 3 + 2];
    float tmin = tminmax[ray * 2 + 0];
    float tmax = tminmax[ray * 2 + 1];

    // Affine transform coefficients: y_c(t) = a_c + t * b_c  (per-lane prim)
    float a0, a1, a2, b0, b1, b2;
    {
        float ppx = primpos[lane * 3 + 0];
        float ppy = primpos[lane * 3 + 1];
        float ppz = primpos[lane * 3 + 2];
        float r00 = primrot[lane * 9 + 0], r01 = primrot[lane * 9 + 1], r02 = primrot[lane * 9 + 2];
        float r10 = primrot[lane * 9 + 3], r11 = primrot[lane * 9 + 4], r12 = primrot[lane * 9 + 5];
        float r20 = primrot[lane * 9 + 6], r21 = primrot[lane * 9 + 7], r22 = primrot[lane * 9 + 8];
        float s0 = primscale[lane * 3 + 0];
        float s1 = primscale[lane * 3 + 1];
        float s2 = primscale[lane * 3 + 2];
        float dx = rpx - ppx, dy = rpy - ppy, dz = rpz - ppz;
        a0 = (r00 * dx + r01 * dy + r02 * dz) * s0;
        a1 = (r10 * dx + r11 * dy + r12 * dz) * s1;
        a2 = (r20 * dx + r21 * dy + r22 * dz) * s2;
        b0 = (r00 * rdx + r01 * rdy + r02 * rdz) * s0;
        b1 = (r10 * rdx + r11 * rdy + r12 * rdz) * s1;
        b2 = (r20 * rdx + r21 * rdy + r22 * rdz) * s2;
    }

    // Steps with t = tmin + i*DT < tmax
    int nsteps = (int)ceilf((tmax - tmin) * 64.0f);
    nsteps = min(nsteps, NSTEPS);

    // Per-lane slab interval [te, tx]: |a_c + t b_c| <= 1 for all c
    float te = -1e30f, tx = 1e30f;
    bool nonempty = true;
    {
        #define SLAB(A, B)                                                   \
        {                                                                    \
            if ((B) != 0.0f) {                                               \
                float u = (-1.0f - (A)) / (B);                               \
                float v = ( 1.0f - (A)) / (B);                               \
                te = fmaxf(te, fminf(u, v));                                 \
                tx = fminf(tx, fmaxf(u, v));                                 \
            } else if (fabsf(A) > 1.0f) {                                    \
                nonempty = false;                                            \
            }                                                                \
        }
        SLAB(a0, b0) SLAB(a1, b1) SLAB(a2, b2)
        #undef SLAB
        if (te > tx) nonempty = false;
    }

    // Step-index bounds (widened 1 step for rounding safety)
    int ie, ixb;
    if (nonempty) {
        float fe  = fminf(fmaxf((te - tmin) * 64.0f, -2.0f), 100.0f);
        float fx_ = fminf(fmaxf((tx - tmin) * 64.0f, -2.0f), 100.0f);
        ie  = (int)floorf(fe) - 1;
        ixb = (int)ceilf(fx_) + 1;
    } else {
        ie  = 1 << 30;
        ixb = -1;
    }
    int istart, iend;
    asm("redux.sync.min.s32 %0, %1, 0xffffffff;" : "=r"(istart) : "r"(ie));
    asm("redux.sync.max.s32 %0, %1, 0xffffffff;" : "=r"(iend)   : "r"(ixb));
    istart = max(istart, 0);
    iend   = min(iend, nsteps - 1);

    float rgbx = 0.f, rgby = 0.f, rgbz = 0.f, alpha = 0.f;
    const uint4* __restrict__ T = g_tpair + (lane << 12);

    // Prefetch increment: y(i+2) = y(i) + 2*DT*b
    float db0 = 2.0f * DTSTEP * b0;
    float db1 = 2.0f * DTSTEP * b1;
    float db2 = 2.0f * DTSTEP * b2;

    // Warm the first two steps' lines
    #pragma unroll
    for (int p = 0; p < 2; p++) {
        float tp = fmaf((float)(istart + p), DTSTEP, tmin);
        float p0 = fmaf(tp, b0, a0);
        float p1 = fmaf(tp, b1, a1);
        float p2 = fmaf(tp, b2, a2);
        if (fabsf(p0) <= 1.0f && fabsf(p1) <= 1.0f && fabsf(p2) <= 1.0f) {
            int pz = min((int)((p0 + 1.0f) * 7.5f), 14);
            int py = min((int)((p1 + 1.0f) * 7.5f), 14);
            int px = min((int)((p2 + 1.0f) * 7.5f), 14);
            const uint4* Pb = T + (pz * 256 + py * 16 + px);
            asm volatile("prefetch.global.L1 [%0];" :: "l"(Pb));
            asm volatile("prefetch.global.L1 [%0];" :: "l"(Pb + 16));
            asm volatile("prefetch.global.L1 [%0];" :: "l"(Pb + 256));
            asm volatile("prefetch.global.L1 [%0];" :: "l"(Pb + 272));
        }
    }

    #pragma unroll 1
    for (int i = istart; i <= iend; i++) {
        float t  = fmaf((float)i, DTSTEP, tmin);
        float y0 = fmaf(t, b0, a0);
        float y1 = fmaf(t, b1, a1);
        float y2 = fmaf(t, b2, a2);

        // ---- prefetch step i+2 (independent of the serial chain) ----
        {
            float p0 = y0 + db0;
            float p1 = y1 + db1;
            float p2 = y2 + db2;
            if (fabsf(p0) <= 1.0f && fabsf(p1) <= 1.0f && fabsf(p2) <= 1.0f) {
                int pz = min((int)((p0 + 1.0f) * 7.5f), 14);
                int py = min((int)((p1 + 1.0f) * 7.5f), 14);
                int px = min((int)((p2 + 1.0f) * 7.5f), 14);
                const uint4* Pb = T + (pz * 256 + py * 16 + px);
                asm volatile("prefetch.global.L1 [%0];" :: "l"(Pb));
                asm volatile("prefetch.global.L1 [%0];" :: "l"(Pb + 16));
                asm volatile("prefetch.global.L1 [%0];" :: "l"(Pb + 256));
                asm volatile("prefetch.global.L1 [%0];" :: "l"(Pb + 272));
            }
        }

        float sx = 0.f, sy = 0.f, sz = 0.f, sw = 0.f;
        if (fabsf(y0) <= 1.0f && fabsf(y1) <= 1.0f && fabsf(y2) <= 1.0f) {
            // component 0 -> z index, 1 -> y, 2 -> x ; g in [0,15] when inside
            float gz = (y0 + 1.0f) * 7.5f;
            float gy = (y1 + 1.0f) * 7.5f;
            float gx = (y2 + 1.0f) * 7.5f;
            int iz = min((int)gz, 14);
            int iy = min((int)gy, 14);
            int ixx = min((int)gx, 14);
            float fz = gz - (float)iz;
            float fy = gy - (float)iy;
            float fx = gx - (float)ixx;

            int base = iz * 256 + iy * 16 + ixx;
            uint4 q00 = __ldg(T + base);            // (iz,  iy)
            uint4 q01 = __ldg(T + base + 16);       // (iz,  iy+1)
            uint4 q10 = __ldg(T + base + 256);      // (iz+1,iy)
            uint4 q11 = __ldg(T + base + 272);      // (iz+1,iy+1)

            __half2 fx2 = __float2half2_rn(fx);
            __half2 fy2 = __float2half2_rn(fy);
            __half2 fz2 = __float2half2_rn(fz);

            __half2 rg00, ba00, rg01, ba01, rg10, ba10, rg11, ba11;
            xlerp_h2(q00, fx2, rg00, ba00);
            xlerp_h2(q01, fx2, rg01, ba01);
            xlerp_h2(q10, fx2, rg10, ba10);
            xlerp_h2(q11, fx2, rg11, ba11);

            __half2 rg0 = __hfma2(fy2, __hsub2(rg01, rg00), rg00);
            __half2 ba0 = __hfma2(fy2, __hsub2(ba01, ba00), ba00);
            __half2 rg1 = __hfma2(fy2, __hsub2(rg11, rg10), rg10);
            __half2 ba1 = __hfma2(fy2, __hsub2(ba11, ba10), ba10);

            __half2 rg = __hfma2(fz2, __hsub2(rg1, rg0), rg0);
            __half2 ba = __hfma2(fz2, __hsub2(ba1, ba0), ba0);

            float2 rgf = __half22float2(rg);
            float2 baf = __half22float2(ba);
            sx = rgf.x; sy = rgf.y; sz = baf.x; sw = baf.y;
        }

        // Warp-sum of alpha channel: fixed-point integer REDUX (1 op vs 5-SHFL chain)
        int isw = __float2int_rn(sw * FXSCALE);
        asm("redux.sync.add.s32 %0, %1, 0xffffffff;" : "=r"(isw) : "r"(isw));
        float swsum = (float)isw * FXINV;

        float na = fminf(fmaf(swsum, DTSTEP, alpha), 1.0f);
        float contrib = na - alpha;         // warp-uniform
        rgbx = fmaf(sx, contrib, rgbx);     // per-lane partial; reduced at the end
        rgby = fmaf(sy, contrib, rgby);
        rgbz = fmaf(sz, contrib, rgbz);
        alpha = na;
        if (alpha >= 1.0f) break;           // saturated: all later contribs 0
    }

    // Final rgb reduction across the warp
    #pragma unroll
    for (int off = 16; off; off >>= 1) {
        rgbx += __shfl_xor_sync(0xffffffffu, rgbx, off);
        rgby += __shfl_xor_sync(0xffffffffu, rgby, off);
        rgbz += __shfl_xor_sync(0xffffffffu, rgbz, off);
    }

    // Spread the 8 stores over lanes 0-7
    // out layout: rayrgb [1,3,H,W] | rayalpha [1,1,H,W] | rayrgba [1,4,H,W]
    float vals[8] = {rgbx, rgby, rgbz, alpha, rgbx, rgby, rgbz, alpha};
    if (lane < 8)
        out[lane * R_TOT + ray] = vals[lane];
}

extern "C" void kernel_launch(void* const* d_in, const int* in_sizes, int n_in,
                              void* d_out, int out_size) {
    const float* raypos    = (const float*)d_in[0];
    const float* raydir    = (const float*)d_in[1];
    const float* tminmax   = (const float*)d_in[2];
    const float* primpos   = (const float*)d_in[3];
    const float* primrot   = (const float*)d_in[4];
    const float* primscale = (const float*)d_in[5];
    const float* tmpl      = (const float*)d_in[6];
    float* out = (float*)d_out;

    pack_tmpl_kernel<<<(KPRIM * 4096 + 255) / 256, 256>>>(tmpl);

    int threads = R_TOT * 32;
    march_kernel<<<threads / 64, 64>>>(raypos, raydir, tminmax,
                                       primpos, primrot, primscale, out);
}

// round 14
// speedup vs baseline: 1.2889x; 1.2889x over previous
#include <cuda_runtime.h>
#include <cuda_fp16.h>

#define R_TOT   16384      // H*W rays
#define KPRIM   32
#define NSTEPS  64
#define DTSTEP  (1.0f/64.0f)
#define FXSCALE 1048576.0f         // 2^20 fixed-point scale for alpha redux
#define FXINV   (1.0f/1048576.0f)

// Packed template: per (k,z,y,x): {h2(r,g)@x, h2(b,a)@x, h2(r,g)@x+1, h2(b,a)@x+1} = 16B
__device__ uint4 g_tpair[KPRIM * 4096];   // 2 MB, L2-resident

// --- Prologue: pack template [K,4,16,16,16] fp32 -> channel-pair half2s ---
__global__ void pack_tmpl_kernel(const float* __restrict__ tmpl) {
    int idx = blockIdx.x * blockDim.x + threadIdx.x;
    if (idx >= KPRIM * 4096) return;
    int k = idx >> 12;
    int v = idx & 4095;            // z*256 + y*16 + x
    int x = v & 15;
    int x1 = (x < 15) ? 1 : 0;     // clamp x+1 (offset)
    const float* b = tmpl + (size_t)k * 4 * 4096;
    int p0 = v, p1 = v + x1;
    __half2 rg0 = __floats2half2_rn(b[p0],          b[4096 + p0]);
    __half2 ba0 = __floats2half2_rn(b[8192 + p0],   b[12288 + p0]);
    __half2 rg1 = __floats2half2_rn(b[p1],          b[4096 + p1]);
    __half2 ba1 = __floats2half2_rn(b[8192 + p1],   b[12288 + p1]);
    uint4 q;
    q.x = *(unsigned int*)&rg0;
    q.y = *(unsigned int*)&ba0;
    q.z = *(unsigned int*)&rg1;
    q.w = *(unsigned int*)&ba1;
    g_tpair[idx] = q;
}

// Full trilinear sample from 4 corner-pair quads (half2 tree), result fp32 x4
__device__ __forceinline__ void trisample(
    uint4 q00, uint4 q01, uint4 q10, uint4 q11,
    float fx, float fy, float fz,
    float& sx, float& sy, float& sz, float& sw)
{
    __half2 fx2 = __float2half2_rn(fx);
    __half2 fy2 = __float2half2_rn(fy);
    __half2 fz2 = __float2half2_rn(fz);

    __half2 rg00 = __hfma2(fx2, __hsub2(*(__half2*)&q00.z, *(__half2*)&q00.x), *(__half2*)&q00.x);
    __half2 ba00 = __hfma2(fx2, __hsub2(*(__half2*)&q00.w, *(__half2*)&q00.y), *(__half2*)&q00.y);
    __half2 rg01 = __hfma2(fx2, __hsub2(*(__half2*)&q01.z, *(__half2*)&q01.x), *(__half2*)&q01.x);
    __half2 ba01 = __hfma2(fx2, __hsub2(*(__half2*)&q01.w, *(__half2*)&q01.y), *(__half2*)&q01.y);
    __half2 rg10 = __hfma2(fx2, __hsub2(*(__half2*)&q10.z, *(__half2*)&q10.x), *(__half2*)&q10.x);
    __half2 ba10 = __hfma2(fx2, __hsub2(*(__half2*)&q10.w, *(__half2*)&q10.y), *(__half2*)&q10.y);
    __half2 rg11 = __hfma2(fx2, __hsub2(*(__half2*)&q11.z, *(__half2*)&q11.x), *(__half2*)&q11.x);
    __half2 ba11 = __hfma2(fx2, __hsub2(*(__half2*)&q11.w, *(__half2*)&q11.y), *(__half2*)&q11.y);

    __half2 rg0 = __hfma2(fy2, __hsub2(rg01, rg00), rg00);
    __half2 ba0 = __hfma2(fy2, __hsub2(ba01, ba00), ba00);
    __half2 rg1 = __hfma2(fy2, __hsub2(rg11, rg10), rg10);
    __half2 ba1 = __hfma2(fy2, __hsub2(ba11, ba10), ba10);

    __half2 rg = __hfma2(fz2, __hsub2(rg1, rg0), rg0);
    __half2 ba = __hfma2(fz2, __hsub2(ba1, ba0), ba0);

    float2 rgf = __half22float2(rg);
    float2 baf = __half22float2(ba);
    sx = rgf.x; sy = rgf.y; sz = baf.x; sw = baf.y;
}

// --- Main march: warp per ray, lane per prim, branch-free 2-step unrolled body ---
__global__ void __launch_bounds__(64) march_kernel(
    const float* __restrict__ raypos,
    const float* __restrict__ raydir,
    const float* __restrict__ tminmax,
    const float* __restrict__ primpos,
    const float* __restrict__ primrot,
    const float* __restrict__ primscale,
    float* __restrict__ out)
{
    int gtid = blockIdx.x * blockDim.x + threadIdx.x;
    int ray  = gtid >> 5;
    int lane = threadIdx.x & 31;
    if (ray >= R_TOT) return;

    float rpx = raypos[ray * 3 + 0];
    float rpy = raypos[ray * 3 + 1];
    float rpz = raypos[ray * 3 + 2];
    float rdx = raydir[ray * 3 + 0];
    float rdy = raydir[ray * 3 + 1];
    float rdz = raydir[ray * 3 + 2];
    float tmin = tminmax[ray * 2 + 0];
    float tmax = tminmax[ray * 2 + 1];

    // Affine transform coefficients: y_c(t) = a_c + t * b_c  (per-lane prim)
    float a0, a1, a2, b0, b1, b2;
    {
        float ppx = primpos[lane * 3 + 0];
        float ppy = primpos[lane * 3 + 1];
        float ppz = primpos[lane * 3 + 2];
        float r00 = primrot[lane * 9 + 0], r01 = primrot[lane * 9 + 1], r02 = primrot[lane * 9 + 2];
        float r10 = primrot[lane * 9 + 3], r11 = primrot[lane * 9 + 4], r12 = primrot[lane * 9 + 5];
        float r20 = primrot[lane * 9 + 6], r21 = primrot[lane * 9 + 7], r22 = primrot[lane * 9 + 8];
        float s0 = primscale[lane * 3 + 0];
        float s1 = primscale[lane * 3 + 1];
        float s2 = primscale[lane * 3 + 2];
        float dx = rpx - ppx, dy = rpy - ppy, dz = rpz - ppz;
        a0 = (r00 * dx + r01 * dy + r02 * dz) * s0;
        a1 = (r10 * dx + r11 * dy + r12 * dz) * s1;
        a2 = (r20 * dx + r21 * dy + r22 * dz) * s2;
        b0 = (r00 * rdx + r01 * rdy + r02 * rdz) * s0;
        b1 = (r10 * rdx + r11 * rdy + r12 * rdz) * s1;
        b2 = (r20 * rdx + r21 * rdy + r22 * rdz) * s2;
    }

    // Steps with t = tmin + i*DT < tmax
    int nsteps = (int)ceilf((tmax - tmin) * 64.0f);
    nsteps = min(nsteps, NSTEPS);

    // Per-lane slab interval [te, tx]: |a_c + t b_c| <= 1 for all c
    float te = -1e30f, tx = 1e30f;
    bool nonempty = true;
    {
        #define SLAB(A, B)                                                   \
        {                                                                    \
            if ((B) != 0.0f) {                                               \
                float u = (-1.0f - (A)) / (B);                               \
                float v = ( 1.0f - (A)) / (B);                               \
                te = fmaxf(te, fminf(u, v));                                 \
                tx = fminf(tx, fmaxf(u, v));                                 \
            } else if (fabsf(A) > 1.0f) {                                    \
                nonempty = false;                                            \
            }                                                                \
        }
        SLAB(a0, b0) SLAB(a1, b1) SLAB(a2, b2)
        #undef SLAB
        if (te > tx) nonempty = false;
    }

    // Step-index bounds (widened 1 step for rounding safety)
    int ie, ixb;
    if (nonempty) {
        float fe  = fminf(fmaxf((te - tmin) * 64.0f, -2.0f), 100.0f);
        float fx_ = fminf(fmaxf((tx - tmin) * 64.0f, -2.0f), 100.0f);
        ie  = (int)floorf(fe) - 1;
        ixb = (int)ceilf(fx_) + 1;
    } else {
        ie  = 1 << 30;
        ixb = -1;
    }
    int istart, iend;
    asm("redux.sync.min.s32 %0, %1, 0xffffffff;" : "=r"(istart) : "r"(ie));
    asm("redux.sync.max.s32 %0, %1, 0xffffffff;" : "=r"(iend)   : "r"(ixb));
    istart = max(istart, 0);
    iend   = min(iend, nsteps - 1);

    float rgbx = 0.f, rgby = 0.f, rgbz = 0.f, alpha = 0.f;
    const uint4* __restrict__ T = g_tpair + (lane << 12);

    #pragma unroll 1
    for (int i = istart; i <= iend; i += 2) {
        // ---- addresses + loads for BOTH steps up front (8 independent LDG.128) ----
        float tA  = fmaf((float)i, DTSTEP, tmin);
        float tB  = tA + DTSTEP;

        float yA0 = fmaf(tA, b0, a0), yA1 = fmaf(tA, b1, a1), yA2 = fmaf(tA, b2, a2);
        float yB0 = fmaf(tB, b0, a0), yB1 = fmaf(tB, b1, a1), yB2 = fmaf(tB, b2, a2);

        float insA = (fabsf(yA0) <= 1.0f && fabsf(yA1) <= 1.0f && fabsf(yA2) <= 1.0f) ? 1.0f : 0.0f;
        float insB = (fabsf(yB0) <= 1.0f && fabsf(yB1) <= 1.0f && fabsf(yB2) <= 1.0f
                      && (i + 1 <= iend)) ? 1.0f : 0.0f;

        float gAz = (yA0 + 1.0f) * 7.5f, gAy = (yA1 + 1.0f) * 7.5f, gAx = (yA2 + 1.0f) * 7.5f;
        float gBz = (yB0 + 1.0f) * 7.5f, gBy = (yB1 + 1.0f) * 7.5f, gBx = (yB2 + 1.0f) * 7.5f;

        int iAz = min(max((int)gAz, 0), 14);
        int iAy = min(max((int)gAy, 0), 14);
        int iAx = min(max((int)gAx, 0), 14);
        int iBz = min(max((int)gBz, 0), 14);
        int iBy = min(max((int)gBy, 0), 14);
        int iBx = min(max((int)gBx, 0), 14);

        float fAz = gAz - (float)iAz, fAy = gAy - (float)iAy, fAx = gAx - (float)iAx;
        float fBz = gBz - (float)iBz, fBy = gBy - (float)iBy, fBx = gBx - (float)iBx;

        int baseA = iAz * 256 + iAy * 16 + iAx;
        int baseB = iBz * 256 + iBy * 16 + iBx;

        // Unconditional clamped loads: always in-bounds, no divergence
        uint4 qA00 = __ldg(T + baseA);
        uint4 qA01 = __ldg(T + baseA + 16);
        uint4 qA10 = __ldg(T + baseA + 256);
        uint4 qA11 = __ldg(T + baseA + 272);
        uint4 qB00 = __ldg(T + baseB);
        uint4 qB01 = __ldg(T + baseB + 16);
        uint4 qB10 = __ldg(T + baseB + 256);
        uint4 qB11 = __ldg(T + baseB + 272);

        // ---- step A ----
        float sAx, sAy, sAz, sAw;
        trisample(qA00, qA01, qA10, qA11, fAx, fAy, fAz, sAx, sAy, sAz, sAw);
        int iswA = __float2int_rn(sAw * insA * FXSCALE);
        asm("redux.sync.add.s32 %0, %1, 0xffffffff;" : "=r"(iswA) : "r"(iswA));

        // ---- step B (tree overlaps A's redux latency) ----
        float sBx, sBy, sBz, sBw;
        trisample(qB00, qB01, qB10, qB11, fBx, fBy, fBz, sBx, sBy, sBz, sBw);
        int iswB = __float2int_rn(sBw * insB * FXSCALE);
        asm("redux.sync.add.s32 %0, %1, 0xffffffff;" : "=r"(iswB) : "r"(iswB));

        // ---- composite A then B (serial, cheap) ----
        float naA = fminf(fmaf((float)iswA * FXINV, DTSTEP, alpha), 1.0f);
        float cA  = naA - alpha;
        rgbx = fmaf(sAx * insA, cA, rgbx);
        rgby = fmaf(sAy * insA, cA, rgby);
        rgbz = fmaf(sAz * insA, cA, rgbz);

        float naB = fminf(fmaf((float)iswB * FXINV, DTSTEP, naA), 1.0f);
        float cB  = naB - naA;
        rgbx = fmaf(sBx * insB, cB, rgbx);
        rgby = fmaf(sBy * insB, cB, rgby);
        rgbz = fmaf(sBz * insB, cB, rgbz);
        alpha = naB;

        if (alpha >= 1.0f) break;           // saturated: all later contribs 0
    }

    // Final rgb reduction across the warp
    #pragma unroll
    for (int off = 16; off; off >>= 1) {
        rgbx += __shfl_xor_sync(0xffffffffu, rgbx, off);
        rgby += __shfl_xor_sync(0xffffffffu, rgby, off);
        rgbz += __shfl_xor_sync(0xffffffffu, rgbz, off);
    }

    // Spread the 8 stores over lanes 0-7
    // out layout: rayrgb [1,3,H,W] | rayalpha [1,1,H,W] | rayrgba [1,4,H,W]
    float vals[8] = {rgbx, rgby, rgbz, alpha, rgbx, rgby, rgbz, alpha};
    if (lane < 8)
        out[lane * R_TOT + ray] = vals[lane];
}

extern "C" void kernel_launch(void* const* d_in, const int* in_sizes, int n_in,
                              void* d_out, int out_size) {
    const float* raypos    = (const float*)d_in[0];
    const float* raydir    = (const float*)d_in[1];
    const float* tminmax   = (const float*)d_in[2];
    const float* primpos   = (const float*)d_in[3];
    const float* primrot   = (const float*)d_in[4];
    const float* primscale = (const float*)d_in[5];
    const float* tmpl      = (const float*)d_in[6];
    float* out = (float*)d_out;

    pack_tmpl_kernel<<<(KPRIM * 4096 + 255) / 256, 256>>>(tmpl);

    int threads = R_TOT * 32;
    march_kernel<<<threads / 64, 64>>>(raypos, raydir, tminmax,
                                       primpos, primrot, primscale, out);
}

// round 15
// speedup vs baseline: 1.7967x; 1.3939x over previous
#include <cuda_runtime.h>
#include <cuda_fp16.h>

#define R_TOT   16384      // H*W rays
#define KPRIM   32
#define NSTEPS  64
#define DTSTEP  (1.0f/64.0f)
#define FXSCALE 1048576.0f         // 2^20 fixed-point scale for alpha redux
#define FXINV   (1.0f/1048576.0f)

// Packed template: per (k,z,y,x): {h2(r,g)@x, h2(b,a)@x, h2(r,g)@x+1, h2(b,a)@x+1} = 16B
__device__ uint4 g_tpair[KPRIM * 4096];   // 2 MB, L2-resident

// --- Prologue: pack template [K,4,16,16,16] fp32 -> channel-pair half2s ---
__global__ void pack_tmpl_kernel(const float* __restrict__ tmpl) {
    int idx = blockIdx.x * blockDim.x + threadIdx.x;
    if (idx >= KPRIM * 4096) return;
    int k = idx >> 12;
    int v = idx & 4095;            // z*256 + y*16 + x
    int x = v & 15;
    int x1 = (x < 15) ? 1 : 0;     // clamp x+1 (offset)
    const float* b = tmpl + (size_t)k * 4 * 4096;
    int p0 = v, p1 = v + x1;
    __half2 rg0 = __floats2half2_rn(b[p0],          b[4096 + p0]);
    __half2 ba0 = __floats2half2_rn(b[8192 + p0],   b[12288 + p0]);
    __half2 rg1 = __floats2half2_rn(b[p1],          b[4096 + p1]);
    __half2 ba1 = __floats2half2_rn(b[8192 + p1],   b[12288 + p1]);
    uint4 q;
    q.x = *(unsigned int*)&rg0;
    q.y = *(unsigned int*)&ba0;
    q.z = *(unsigned int*)&rg1;
    q.w = *(unsigned int*)&ba1;
    g_tpair[idx] = q;
}

// --- Main march: warp per ray, lane per prim, branchless body (addr-select) ---
__global__ void __launch_bounds__(64) march_kernel(
    const float* __restrict__ raypos,
    const float* __restrict__ raydir,
    const float* __restrict__ tminmax,
    const float* __restrict__ primpos,
    const float* __restrict__ primrot,
    const float* __restrict__ primscale,
    float* __restrict__ out)
{
    int gtid = blockIdx.x * blockDim.x + threadIdx.x;
    int ray  = gtid >> 5;
    int lane = threadIdx.x & 31;
    if (ray >= R_TOT) return;

    float rpx = raypos[ray * 3 + 0];
    float rpy = raypos[ray * 3 + 1];
    float rpz = raypos[ray * 3 + 2];
    float rdx = raydir[ray * 3 + 0];
    float rdy = raydir[ray * 3 + 1];
    float rdz = raydir[ray * 3 + 2];
    float tmin = tminmax[ray * 2 + 0];
    float tmax = tminmax[ray * 2 + 1];

    // Affine transform coefficients: y_c(t) = a_c + t * b_c  (per-lane prim)
    float a0, a1, a2, b0, b1, b2;
    {
        float ppx = primpos[lane * 3 + 0];
        float ppy = primpos[lane * 3 + 1];
        float ppz = primpos[lane * 3 + 2];
        float r00 = primrot[lane * 9 + 0], r01 = primrot[lane * 9 + 1], r02 = primrot[lane * 9 + 2];
        float r10 = primrot[lane * 9 + 3], r11 = primrot[lane * 9 + 4], r12 = primrot[lane * 9 + 5];
        float r20 = primrot[lane * 9 + 6], r21 = primrot[lane * 9 + 7], r22 = primrot[lane * 9 + 8];
        float s0 = primscale[lane * 3 + 0];
        float s1 = primscale[lane * 3 + 1];
        float s2 = primscale[lane * 3 + 2];
        float dx = rpx - ppx, dy = rpy - ppy, dz = rpz - ppz;
        a0 = (r00 * dx + r01 * dy + r02 * dz) * s0;
        a1 = (r10 * dx + r11 * dy + r12 * dz) * s1;
        a2 = (r20 * dx + r21 * dy + r22 * dz) * s2;
        b0 = (r00 * rdx + r01 * rdy + r02 * rdz) * s0;
        b1 = (r10 * rdx + r11 * rdy + r12 * rdz) * s1;
        b2 = (r20 * rdx + r21 * rdy + r22 * rdz) * s2;
    }

    // Steps with t = tmin + i*DT < tmax
    int nsteps = (int)ceilf((tmax - tmin) * 64.0f);
    nsteps = min(nsteps, NSTEPS);

    // Per-lane slab interval [te, tx]: |a_c + t b_c| <= 1 for all c
    float te = -1e30f, tx = 1e30f;
    bool nonempty = true;
    {
        #define SLAB(A, B)                                                   \
        {                                                                    \
            if ((B) != 0.0f) {                                               \
                float u = (-1.0f - (A)) / (B);                               \
                float v = ( 1.0f - (A)) / (B);                               \
                te = fmaxf(te, fminf(u, v));                                 \
                tx = fminf(tx, fmaxf(u, v));                                 \
            } else if (fabsf(A) > 1.0f) {                                    \
                nonempty = false;                                            \
            }                                                                \
        }
        SLAB(a0, b0) SLAB(a1, b1) SLAB(a2, b2)
        #undef SLAB
        if (te > tx) nonempty = false;
    }

    // Step-index bounds (widened 1 step for rounding safety)
    int ie, ixb;
    if (nonempty) {
        float fe  = fminf(fmaxf((te - tmin) * 64.0f, -2.0f), 100.0f);
        float fx_ = fminf(fmaxf((tx - tmin) * 64.0f, -2.0f), 100.0f);
        ie  = (int)floorf(fe) - 1;
        ixb = (int)ceilf(fx_) + 1;
    } else {
        ie  = 1 << 30;
        ixb = -1;
    }
    int istart, iend;
    asm("redux.sync.min.s32 %0, %1, 0xffffffff;" : "=r"(istart) : "r"(ie));
    asm("redux.sync.max.s32 %0, %1, 0xffffffff;" : "=r"(iend)   : "r"(ixb));
    istart = max(istart, 0);
    iend   = min(iend, nsteps - 1);

    float rgbx = 0.f, rgby = 0.f, rgbz = 0.f, alpha = 0.f;
    const uint4* __restrict__ T = g_tpair + (lane << 12);

    #pragma unroll 1
    for (int i = istart; i <= iend; i++) {
        float t  = fmaf((float)i, DTSTEP, tmin);
        float y0 = fmaf(t, b0, a0);
        float y1 = fmaf(t, b1, a1);
        float y2 = fmaf(t, b2, a2);

        bool ins = fabsf(y0) <= 1.0f && fabsf(y1) <= 1.0f && fabsf(y2) <= 1.0f;
        float insf = ins ? 1.0f : 0.0f;

        // component 0 -> z index, 1 -> y, 2 -> x ; g in [0,15] for inside lanes
        float gz = (y0 + 1.0f) * 7.5f;
        float gy = (y1 + 1.0f) * 7.5f;
        float gx = (y2 + 1.0f) * 7.5f;
        int iz = min((int)gz, 14);
        int iy = min((int)gy, 14);
        int ixx = min((int)gx, 14);
        // Saturate so outside-lane garbage can't produce NaN through the tree
        float fz = __saturatef(gz - (float)iz);
        float fy = __saturatef(gy - (float)iy);
        float fx = __saturatef(gx - (float)ixx);

        // Branchless address select: outside lanes all hit g_tpair[0] (broadcast line)
        int base = iz * 256 + iy * 16 + ixx;
        const uint4* e = ins ? (T + base) : g_tpair;

        uint4 q00 = __ldg(e);            // (iz,  iy)
        uint4 q01 = __ldg(e + 16);       // (iz,  iy+1)
        uint4 q10 = __ldg(e + 256);      // (iz+1,iy)
        uint4 q11 = __ldg(e + 272);      // (iz+1,iy+1)

        __half2 fx2 = __float2half2_rn(fx);
        __half2 fy2 = __float2half2_rn(fy);
        __half2 fz2 = __float2half2_rn(fz);

        __half2 rg00 = __hfma2(fx2, __hsub2(*(__half2*)&q00.z, *(__half2*)&q00.x), *(__half2*)&q00.x);
        __half2 ba00 = __hfma2(fx2, __hsub2(*(__half2*)&q00.w, *(__half2*)&q00.y), *(__half2*)&q00.y);
        __half2 rg01 = __hfma2(fx2, __hsub2(*(__half2*)&q01.z, *(__half2*)&q01.x), *(__half2*)&q01.x);
        __half2 ba01 = __hfma2(fx2, __hsub2(*(__half2*)&q01.w, *(__half2*)&q01.y), *(__half2*)&q01.y);
        __half2 rg10 = __hfma2(fx2, __hsub2(*(__half2*)&q10.z, *(__half2*)&q10.x), *(__half2*)&q10.x);
        __half2 ba10 = __hfma2(fx2, __hsub2(*(__half2*)&q10.w, *(__half2*)&q10.y), *(__half2*)&q10.y);
        __half2 rg11 = __hfma2(fx2, __hsub2(*(__half2*)&q11.z, *(__half2*)&q11.x), *(__half2*)&q11.x);
        __half2 ba11 = __hfma2(fx2, __hsub2(*(__half2*)&q11.w, *(__half2*)&q11.y), *(__half2*)&q11.y);

        __half2 rg0 = __hfma2(fy2, __hsub2(rg01, rg00), rg00);
        __half2 ba0 = __hfma2(fy2, __hsub2(ba01, ba00), ba00);
        __half2 rg1 = __hfma2(fy2, __hsub2(rg11, rg10), rg10);
        __half2 ba1 = __hfma2(fy2, __hsub2(ba11, ba10), ba10);

        __half2 rg = __hfma2(fz2, __hsub2(rg1, rg0), rg0);
        __half2 ba = __hfma2(fz2, __hsub2(ba1, ba0), ba0);

        float2 rgf = __half22float2(rg);
        float2 baf = __half22float2(ba);
        float sx = rgf.x * insf;
        float sy = rgf.y * insf;
        float sz = baf.x * insf;
        float sw = baf.y * insf;

        // Warp-sum of alpha channel: fixed-point integer REDUX
        int isw = __float2int_rn(sw * FXSCALE);
        asm("redux.sync.add.s32 %0, %1, 0xffffffff;" : "=r"(isw) : "r"(isw));
        float swsum = (float)isw * FXINV;

        float na = fminf(fmaf(swsum, DTSTEP, alpha), 1.0f);
        float contrib = na - alpha;         // warp-uniform
        rgbx = fmaf(sx, contrib, rgbx);     // per-lane partial; reduced at the end
        rgby = fmaf(sy, contrib, rgby);
        rgbz = fmaf(sz, contrib, rgbz);
        alpha = na;
        if (alpha >= 1.0f) break;           // saturated: all later contribs 0
    }

    // Final rgb reduction across the warp
    #pragma unroll
    for (int off = 16; off; off >>= 1) {
        rgbx += __shfl_xor_sync(0xffffffffu, rgbx, off);
        rgby += __shfl_xor_sync(0xffffffffu, rgby, off);
        rgbz += __shfl_xor_sync(0xffffffffu, rgbz, off);
    }

    // Spread the 8 stores over lanes 0-7
    // out layout: rayrgb [1,3,H,W] | rayalpha [1,1,H,W] | rayrgba [1,4,H,W]
    float vals[8] = {rgbx, rgby, rgbz, alpha, rgbx, rgby, rgbz, alpha};
    if (lane < 8)
        out[lane * R_TOT + ray] = vals[lane];
}

extern "C" void kernel_launch(void* const* d_in, const int* in_sizes, int n_in,
                              void* d_out, int out_size) {
    const float* raypos    = (const float*)d_in[0];
    const float* raydir    = (const float*)d_in[1];
    const float* tminmax   = (const float*)d_in[2];
    const float* primpos   = (const float*)d_in[3];
    const float* primrot   = (const float*)d_in[4];
    const float* primscale = (const float*)d_in[5];
    const float* tmpl      = (const float*)d_in[6];
    float* out = (float*)d_out;

    pack_tmpl_kernel<<<(KPRIM * 4096 + 255) / 256, 256>>>(tmpl);

    int threads = R_TOT * 32;
    march_kernel<<<threads / 64, 64>>>(raypos, raydir, tminmax,
                                       primpos, primrot, primscale, out);
}